// round 7
// baseline (speedup 1.0000x reference)
#include <cuda_runtime.h>
#include <cuda_bf16.h>
#include <cstdint>
#include <cstddef>

#define EPSV 1e-5f
#define BB 32768
#define DD 1985
#define KP0 2000
#define N0 512
#define N1 256
#define N2 256
#define NE 29
#define MAX_TILES 1056

// ----------------------- static device scratch -----------------------
__device__ __align__(128) float g_W0p[KP0 * N0];
__device__ __align__(128) float g_W1p[N0 * N1];
__device__ __align__(128) float g_W2p[N1 * N2];
__device__ float g_alpha0[N0], g_beta0[N0];
__device__ float g_alpha1[N1], g_beta1[N1];
__device__ float g_alpha2[N2], g_beta2[N2];
__device__ __align__(128) float g_Y1[BB * N0];
__device__ __align__(128) float g_Y2[BB * N1];
__device__ __align__(128) float g_Y3[BB * N2];
__device__ int g_cnt[NE], g_off[NE], g_cur[NE];
__device__ int g_idx[BB];

// ----------------------- helpers -----------------------
__device__ __forceinline__ float tf32r(float x) {
    uint32_t u;
    asm("cvt.rna.tf32.f32 %0, %1;" : "=r"(u) : "f"(x));
    return __uint_as_float(u);
}

__device__ __forceinline__ void cp16(float* s, const float* g) {
    uint32_t sa = (uint32_t)__cvta_generic_to_shared(s);
    asm volatile("cp.async.cg.shared.global [%0], [%1], 16;" :: "r"(sa), "l"(g));
}

// 4-byte cp.async with zero-fill when pred==0 (src-size operand)
__device__ __forceinline__ void cp4z(float* s, const float* g, int pred) {
    uint32_t sa = (uint32_t)__cvta_generic_to_shared(s);
    int sz = pred ? 4 : 0;
    asm volatile("cp.async.ca.shared.global [%0], [%1], 4, %2;"
                 :: "r"(sa), "l"(g), "r"(sz));
}

__device__ __forceinline__ void mma_tf32(float (&d)[4], const uint32_t (&a)[4],
                                         const uint32_t (&b)[2]) {
    asm volatile(
        "mma.sync.aligned.m16n8k8.row.col.f32.tf32.tf32.f32 "
        "{%0,%1,%2,%3}, {%4,%5,%6,%7}, {%8,%9}, {%0,%1,%2,%3};"
        : "+f"(d[0]), "+f"(d[1]), "+f"(d[2]), "+f"(d[3])
        : "r"(a[0]), "r"(a[1]), "r"(a[2]), "r"(a[3]), "r"(b[0]), "r"(b[1]));
}

// ----------------------- prep: fold BN, round weights, zero counters -----------------------
__global__ void k_prep(
    const float* __restrict__ W0, const float* __restrict__ b0, const float* __restrict__ gg0,
    const float* __restrict__ be0, const float* __restrict__ m0, const float* __restrict__ v0,
    const float* __restrict__ W1, const float* __restrict__ b1, const float* __restrict__ gg1,
    const float* __restrict__ be1, const float* __restrict__ m1, const float* __restrict__ v1,
    const float* __restrict__ W2, const float* __restrict__ b2, const float* __restrict__ gg2,
    const float* __restrict__ be2, const float* __restrict__ m2, const float* __restrict__ v2)
{
    int t = blockIdx.x * blockDim.x + threadIdx.x;
    int stride = gridDim.x * blockDim.x;
    for (int i = t; i < KP0 * N0; i += stride) {
        int k = i >> 9, n = i & 511;               // N0 = 512
        g_W0p[i] = (k < DD) ? tf32r(W0[k * N0 + n]) : 0.f;
    }
    for (int i = t; i < N0 * N1; i += stride) g_W1p[i] = tf32r(W1[i]);
    for (int i = t; i < N1 * N2; i += stride) g_W2p[i] = tf32r(W2[i]);
    if (t < N0) {
        float a = gg0[t] * rsqrtf(v0[t] + EPSV);
        g_alpha0[t] = a; g_beta0[t] = (b0[t] - m0[t]) * a + be0[t];
    }
    if (t < N1) {
        float a = gg1[t] * rsqrtf(v1[t] + EPSV);
        g_alpha1[t] = a; g_beta1[t] = (b1[t] - m1[t]) * a + be1[t];
    }
    if (t < N2) {
        float a = gg2[t] * rsqrtf(v2[t] + EPSV);
        g_alpha2[t] = a; g_beta2[t] = (b2[t] - m2[t]) * a + be2[t];
    }
    if (t < NE) g_cnt[t] = 0;
}

// ----------------------- label bucketing -----------------------
__global__ void k_hist(const int* __restrict__ labels) {
    __shared__ int lc[NE];
    if (threadIdx.x < NE) lc[threadIdx.x] = 0;
    __syncthreads();
    int t = blockIdx.x * blockDim.x + threadIdx.x;
    int stride = gridDim.x * blockDim.x;
    for (int i = t; i < BB; i += stride) atomicAdd(&lc[labels[i]], 1);
    __syncthreads();
    if (threadIdx.x < NE && lc[threadIdx.x]) atomicAdd(&g_cnt[threadIdx.x], lc[threadIdx.x]);
}

// 32-thread warp scan of 29 counts -> offsets
__global__ void k_scan32() {
    int t = threadIdx.x;
    int c = (t < NE) ? g_cnt[t] : 0;
    int x = c;
    #pragma unroll
    for (int o = 1; o < 32; o <<= 1) {
        int y = __shfl_up_sync(0xffffffffu, x, o);
        if (t >= o) x += y;
    }
    int excl = x - c;
    if (t < NE) { g_off[t] = excl; g_cur[t] = excl; }
}

__global__ void k_scatter(const int* __restrict__ labels) {
    int t = blockIdx.x * blockDim.x + threadIdx.x;
    int stride = gridDim.x * blockDim.x;
    for (int i = t; i < BB; i += stride) {
        int p = atomicAdd(&g_cur[labels[i]], 1);
        g_idx[p] = i;
    }
}

// ----------------------- GEMM0: A = raw x (K=1985, unaligned, zero-pad to 2000) ---------------
// 128x128 block tile, BK=16, 8 warps (4x2), warp tile 32x64, mma m16n8k8.
// A-fragments tf32-rounded in-register (RN) after LDS; B pre-rounded in g_W0p.
__global__ void __launch_bounds__(256) k_gemm0(const float* __restrict__ X) {
    __shared__ float As[2][128 * 20];
    __shared__ float Bs[2][16 * 132];

    const int tid  = threadIdx.x;
    const int lane = tid & 31, wid = tid >> 5;
    const int wm = wid & 3, wn = wid >> 2;
    const int m0 = blockIdx.y << 7, n0 = blockIdx.x << 7;
    const int KB = KP0 >> 4;   // 125

    float acc[2][8][4];
    #pragma unroll
    for (int i = 0; i < 2; i++)
        #pragma unroll
        for (int j = 0; j < 8; j++)
            #pragma unroll
            for (int q = 0; q < 4; q++) acc[i][j][q] = 0.f;

    const int arow = tid >> 1;             // 0..127
    const int acb  = (tid & 1) << 3;       // 0 or 8
    const float* xrow = X + (size_t)(m0 + arow) * DD;

    auto load_tile = [&](int kb, int buf) {
        int kbase = kb * 16 + acb;
        float* as = &As[buf][arow * 20 + acb];
        #pragma unroll
        for (int j = 0; j < 8; j++) {
            int k = kbase + j;
            int ok = (k < DD);
            cp4z(as + j, ok ? (xrow + k) : X, ok);
        }
        #pragma unroll
        for (int i = 0; i < 2; i++) {
            int c = tid + i * 256;
            int row = c >> 5, nc = (c & 31) << 2;
            cp16(&Bs[buf][row * 132 + nc], g_W0p + (size_t)(kb * 16 + row) * N0 + n0 + nc);
        }
    };

    load_tile(0, 0);
    asm volatile("cp.async.commit_group;");

    for (int kb = 0; kb < KB; kb++) {
        int buf = kb & 1;
        if (kb + 1 < KB) {
            load_tile(kb + 1, buf ^ 1);
            asm volatile("cp.async.commit_group;");
            asm volatile("cp.async.wait_group 1;");
        } else {
            asm volatile("cp.async.wait_group 0;");
        }
        __syncthreads();

        #pragma unroll
        for (int ks = 0; ks < 2; ks++) {
            uint32_t a[2][4], b[8][2];
            const int ar = wm * 32 + (lane >> 2);
            const int ac = ks * 8 + (lane & 3);
            #pragma unroll
            for (int mt = 0; mt < 2; mt++) {
                const float* ap = &As[buf][(ar + mt * 16) * 20 + ac];
                a[mt][0] = __float_as_uint(tf32r(ap[0]));
                a[mt][1] = __float_as_uint(tf32r(ap[8 * 20]));
                a[mt][2] = __float_as_uint(tf32r(ap[4]));
                a[mt][3] = __float_as_uint(tf32r(ap[8 * 20 + 4]));
            }
            const int br = ks * 8 + (lane & 3);
            const int bc = wn * 64 + (lane >> 2);
            #pragma unroll
            for (int nt = 0; nt < 8; nt++) {
                const float* bp = &Bs[buf][br * 132 + bc + nt * 8];
                b[nt][0] = __float_as_uint(bp[0]);
                b[nt][1] = __float_as_uint(bp[4 * 132]);
            }
            #pragma unroll
            for (int mt = 0; mt < 2; mt++)
                #pragma unroll
                for (int nt = 0; nt < 8; nt++)
                    mma_tf32(acc[mt][nt], a[mt], b[nt]);
        }
        __syncthreads();
    }

    const int rbase = m0 + wm * 32 + (lane >> 2);
    #pragma unroll
    for (int nt = 0; nt < 8; nt++) {
        int col0 = n0 + wn * 64 + nt * 8 + ((lane & 3) << 1);
        float a0 = g_alpha0[col0], a1 = g_alpha0[col0 + 1];
        float c0 = g_beta0[col0],  c1 = g_beta0[col0 + 1];
        #pragma unroll
        for (int mt = 0; mt < 2; mt++) {
            int r = rbase + mt * 16;
            g_Y1[(size_t)r * N0 + col0]           = tf32r(fmaxf(acc[mt][nt][0] * a0 + c0, 0.f));
            g_Y1[(size_t)r * N0 + col0 + 1]       = tf32r(fmaxf(acc[mt][nt][1] * a1 + c1, 0.f));
            g_Y1[(size_t)(r + 8) * N0 + col0]     = tf32r(fmaxf(acc[mt][nt][2] * a0 + c0, 0.f));
            g_Y1[(size_t)(r + 8) * N0 + col0 + 1] = tf32r(fmaxf(acc[mt][nt][3] * a1 + c1, 0.f));
        }
    }
}

// ----------------------- GEMM (layers 1-2, A aligned & pre-rounded) -----------------------
__global__ void __launch_bounds__(256) k_gemm(
    const float* __restrict__ A, const float* __restrict__ Bw,
    const float* __restrict__ al, const float* __restrict__ be,
    float* __restrict__ C, int K, int N, int rnd)
{
    __shared__ float As[2][128 * 20];
    __shared__ float Bs[2][16 * 132];

    const int tid  = threadIdx.x;
    const int lane = tid & 31, wid = tid >> 5;
    const int wm = wid & 3, wn = wid >> 2;
    const int m0 = blockIdx.y << 7, n0 = blockIdx.x << 7;
    const int KB = K >> 4;

    float acc[2][8][4];
    #pragma unroll
    for (int i = 0; i < 2; i++)
        #pragma unroll
        for (int j = 0; j < 8; j++)
            #pragma unroll
            for (int q = 0; q < 4; q++) acc[i][j][q] = 0.f;

    auto load_tile = [&](int kb, int buf) {
        #pragma unroll
        for (int i = 0; i < 2; i++) {
            int c = tid + i * 256;
            int row = c >> 2, kc = (c & 3) << 2;
            cp16(&As[buf][row * 20 + kc], A + (size_t)(m0 + row) * K + kb * 16 + kc);
        }
        #pragma unroll
        for (int i = 0; i < 2; i++) {
            int c = tid + i * 256;
            int row = c >> 5, nc = (c & 31) << 2;
            cp16(&Bs[buf][row * 132 + nc], Bw + (size_t)(kb * 16 + row) * N + n0 + nc);
        }
    };

    load_tile(0, 0);
    asm volatile("cp.async.commit_group;");

    for (int kb = 0; kb < KB; kb++) {
        int buf = kb & 1;
        if (kb + 1 < KB) {
            load_tile(kb + 1, buf ^ 1);
            asm volatile("cp.async.commit_group;");
            asm volatile("cp.async.wait_group 1;");
        } else {
            asm volatile("cp.async.wait_group 0;");
        }
        __syncthreads();

        #pragma unroll
        for (int ks = 0; ks < 2; ks++) {
            uint32_t a[2][4], b[8][2];
            const int ar = wm * 32 + (lane >> 2);
            const int ac = ks * 8 + (lane & 3);
            #pragma unroll
            for (int mt = 0; mt < 2; mt++) {
                const float* ap = &As[buf][(ar + mt * 16) * 20 + ac];
                a[mt][0] = __float_as_uint(ap[0]);
                a[mt][1] = __float_as_uint(ap[8 * 20]);
                a[mt][2] = __float_as_uint(ap[4]);
                a[mt][3] = __float_as_uint(ap[8 * 20 + 4]);
            }
            const int br = ks * 8 + (lane & 3);
            const int bc = wn * 64 + (lane >> 2);
            #pragma unroll
            for (int nt = 0; nt < 8; nt++) {
                const float* bp = &Bs[buf][br * 132 + bc + nt * 8];
                b[nt][0] = __float_as_uint(bp[0]);
                b[nt][1] = __float_as_uint(bp[4 * 132]);
            }
            #pragma unroll
            for (int mt = 0; mt < 2; mt++)
                #pragma unroll
                for (int nt = 0; nt < 8; nt++)
                    mma_tf32(acc[mt][nt], a[mt], b[nt]);
        }
        __syncthreads();
    }

    const int rbase = m0 + wm * 32 + (lane >> 2);
    #pragma unroll
    for (int nt = 0; nt < 8; nt++) {
        int col0 = n0 + wn * 64 + nt * 8 + ((lane & 3) << 1);
        float a0 = al[col0], a1 = al[col0 + 1];
        float c0 = be[col0], c1 = be[col0 + 1];
        #pragma unroll
        for (int mt = 0; mt < 2; mt++) {
            int r = rbase + mt * 16;
            float v0 = fmaxf(acc[mt][nt][0] * a0 + c0, 0.f);
            float v1 = fmaxf(acc[mt][nt][1] * a1 + c1, 0.f);
            float v2 = fmaxf(acc[mt][nt][2] * a0 + c0, 0.f);
            float v3 = fmaxf(acc[mt][nt][3] * a1 + c1, 0.f);
            if (rnd) { v0 = tf32r(v0); v1 = tf32r(v1); v2 = tf32r(v2); v3 = tf32r(v3); }
            C[(size_t)r * N + col0]           = v0;
            C[(size_t)r * N + col0 + 1]       = v1;
            C[(size_t)(r + 8) * N + col0]     = v2;
            C[(size_t)(r + 8) * N + col0 + 1] = v3;
        }
    }
}

// ----------------------- fused per-expert head -----------------------
#define OFF_HW1 0
#define OFF_HW2 32768
#define OFF_FT  40960
#define OFF_H1  49280
#define OFF_P   53504
#define SMEM_HEAD_FLOATS (OFF_P + 641)
#define SMEM_HEAD_BYTES  (SMEM_HEAD_FLOATS * 4)

__global__ void __launch_bounds__(256) k_head(
    const float* __restrict__ HW1, const float* __restrict__ Hb1,
    const float* __restrict__ LG1, const float* __restrict__ LB1,
    const float* __restrict__ HW2, const float* __restrict__ Hb2,
    const float* __restrict__ LG2, const float* __restrict__ LB2,
    const float* __restrict__ HWo, const float* __restrict__ Hbo,
    float* __restrict__ preds)
{
    extern __shared__ float sm[];
    const int bid = blockIdx.x;
    const int tid = threadIdx.x;

    __shared__ int s_e, s_s0, s_cnt;
    if (tid == 0) {
        int off = 0, tacc = 0, e = -1, s0 = 0, cnt = 0;
        #pragma unroll 1
        for (int i = 0; i < NE; i++) {
            int c = g_cnt[i];
            int nt = (c + 31) >> 5;
            if (bid < tacc + nt) {
                e = i;
                int j = bid - tacc;
                s0 = off + j * 32;
                int rem = c - j * 32;
                cnt = rem < 32 ? rem : 32;
                break;
            }
            tacc += nt; off += c;
        }
        s_e = e; s_s0 = s0; s_cnt = cnt;
    }
    __syncthreads();
    if (s_e < 0) return;
    const int e = s_e, s0 = s_s0, cnt = s_cnt;

    float* LG1s = sm + OFF_P;
    float* LB1s = LG1s + 128;
    float* Hb1s = LB1s + 128;
    float* LG2s = Hb1s + 128;
    float* LB2s = LG2s + 64;
    float* Hb2s = LB2s + 64;
    float* HWos = Hb2s + 64;

    {
        const float4* s1 = reinterpret_cast<const float4*>(HW1 + (size_t)e * 256 * 128);
        float4* d1 = reinterpret_cast<float4*>(sm + OFF_HW1);
        for (int c = tid; c < 8192; c += 256) d1[c] = s1[c];
        const float4* s2 = reinterpret_cast<const float4*>(HW2 + (size_t)e * 128 * 64);
        float4* d2 = reinterpret_cast<float4*>(sm + OFF_HW2);
        for (int c = tid; c < 2048; c += 256) d2[c] = s2[c];
        for (int c = tid; c < 32 * 64; c += 256) {
            int s = c >> 6, q = c & 63;
            float4 v = make_float4(0.f, 0.f, 0.f, 0.f);
            if (s < cnt)
                v = reinterpret_cast<const float4*>(g_Y3 + (size_t)g_idx[s0 + s] * 256)[q];
            reinterpret_cast<float4*>(sm + OFF_FT + s * 260)[q] = v;
        }
        if (tid < 128) {
            LG1s[tid] = LG1[e * 128 + tid];
            LB1s[tid] = LB1[e * 128 + tid];
            Hb1s[tid] = Hb1[e * 128 + tid];
        }
        if (tid < 64) {
            LG2s[tid] = LG2[e * 64 + tid];
            LB2s[tid] = LB2[e * 64 + tid];
            Hb2s[tid] = Hb2[e * 64 + tid];
            HWos[tid] = HWo[e * 64 + tid];
        }
    }
    __syncthreads();

    // layer 1: h1 = relu(LN(ft @ HW1 + Hb1))  [32 x 128]
    {
        const int hq = tid & 31;
        const int sg = tid >> 5;
        float acc1[4][4];
        #pragma unroll
        for (int i = 0; i < 4; i++)
            #pragma unroll
            for (int j = 0; j < 4; j++) acc1[i][j] = Hb1s[hq * 4 + j];

        const float4* w4 = reinterpret_cast<const float4*>(sm + OFF_HW1);
        const float* ftb = sm + OFF_FT + sg * 4 * 260;
        #pragma unroll 4
        for (int k = 0; k < 256; k++) {
            float4 w = w4[k * 32 + hq];
            #pragma unroll
            for (int i = 0; i < 4; i++) {
                float f = ftb[i * 260 + k];
                acc1[i][0] += f * w.x;
                acc1[i][1] += f * w.y;
                acc1[i][2] += f * w.z;
                acc1[i][3] += f * w.w;
            }
        }
        #pragma unroll
        for (int i = 0; i < 4; i++) {
            float s1 = acc1[i][0] + acc1[i][1] + acc1[i][2] + acc1[i][3];
            float s2 = acc1[i][0] * acc1[i][0] + acc1[i][1] * acc1[i][1]
                     + acc1[i][2] * acc1[i][2] + acc1[i][3] * acc1[i][3];
            #pragma unroll
            for (int o = 16; o > 0; o >>= 1) {
                s1 += __shfl_xor_sync(0xffffffffu, s1, o);
                s2 += __shfl_xor_sync(0xffffffffu, s2, o);
            }
            float mu  = s1 * (1.f / 128.f);
            float inv = rsqrtf(s2 * (1.f / 128.f) - mu * mu + EPSV);
            float4 o4;
            o4.x = fmaxf((acc1[i][0] - mu) * inv * LG1s[hq * 4 + 0] + LB1s[hq * 4 + 0], 0.f);
            o4.y = fmaxf((acc1[i][1] - mu) * inv * LG1s[hq * 4 + 1] + LB1s[hq * 4 + 1], 0.f);
            o4.z = fmaxf((acc1[i][2] - mu) * inv * LG1s[hq * 4 + 2] + LB1s[hq * 4 + 2], 0.f);
            o4.w = fmaxf((acc1[i][3] - mu) * inv * LG1s[hq * 4 + 3] + LB1s[hq * 4 + 3], 0.f);
            *reinterpret_cast<float4*>(sm + OFF_H1 + (sg * 4 + i) * 132 + hq * 4) = o4;
        }
    }
    __syncthreads();

    // layer 2 + output
    {
        const int kq  = tid & 15;
        const int sg2 = tid >> 4;
        float acc2[2][4];
        #pragma unroll
        for (int i = 0; i < 2; i++)
            #pragma unroll
            for (int j = 0; j < 4; j++) acc2[i][j] = Hb2s[kq * 4 + j];

        const float4* w4 = reinterpret_cast<const float4*>(sm + OFF_HW2);
        const float* h1b = sm + OFF_H1 + sg2 * 2 * 132;
        #pragma unroll 4
        for (int h = 0; h < 128; h++) {
            float4 w = w4[h * 16 + kq];
            #pragma unroll
            for (int i = 0; i < 2; i++) {
                float f = h1b[i * 132 + h];
                acc2[i][0] += f * w.x;
                acc2[i][1] += f * w.y;
                acc2[i][2] += f * w.z;
                acc2[i][3] += f * w.w;
            }
        }
        float hbo = Hbo[e];
        #pragma unroll
        for (int i = 0; i < 2; i++) {
            float s1 = acc2[i][0] + acc2[i][1] + acc2[i][2] + acc2[i][3];
            float s2 = acc2[i][0] * acc2[i][0] + acc2[i][1] * acc2[i][1]
                     + acc2[i][2] * acc2[i][2] + acc2[i][3] * acc2[i][3];
            #pragma unroll
            for (int o = 8; o > 0; o >>= 1) {
                s1 += __shfl_xor_sync(0xffffffffu, s1, o);
                s2 += __shfl_xor_sync(0xffffffffu, s2, o);
            }
            float mu  = s1 * (1.f / 64.f);
            float inv = rsqrtf(s2 * (1.f / 64.f) - mu * mu + EPSV);
            float partial = 0.f;
            #pragma unroll
            for (int j = 0; j < 4; j++) {
                float v = fmaxf((acc2[i][j] - mu) * inv * LG2s[kq * 4 + j] + LB2s[kq * 4 + j], 0.f);
                partial += v * HWos[kq * 4 + j];
            }
            #pragma unroll
            for (int o = 8; o > 0; o >>= 1)
                partial += __shfl_xor_sync(0xffffffffu, partial, o);
            if (kq == 0) {
                int s = sg2 * 2 + i;
                if (s < cnt) preds[g_idx[s0 + s]] = partial + hbo;
            }
        }
    }
}

// ----------------------- launch -----------------------
extern "C" void kernel_launch(void* const* d_in, const int* in_sizes, int n_in,
                              void* d_out, int out_size) {
    const float* x      = (const float*)d_in[0];
    const int*   labels = (const int*)  d_in[1];
    const float *W0 = (const float*)d_in[2],  *b0 = (const float*)d_in[3],
                *gg0 = (const float*)d_in[4], *be0 = (const float*)d_in[5],
                *m0 = (const float*)d_in[6],  *v0 = (const float*)d_in[7];
    const float *W1 = (const float*)d_in[8],  *b1 = (const float*)d_in[9],
                *gg1 = (const float*)d_in[10], *be1 = (const float*)d_in[11],
                *m1 = (const float*)d_in[12], *v1 = (const float*)d_in[13];
    const float *W2 = (const float*)d_in[14], *b2 = (const float*)d_in[15],
                *gg2 = (const float*)d_in[16], *be2 = (const float*)d_in[17],
                *m2 = (const float*)d_in[18], *v2 = (const float*)d_in[19];
    const float *HW1 = (const float*)d_in[20], *Hb1 = (const float*)d_in[21],
                *LG1 = (const float*)d_in[22], *LB1 = (const float*)d_in[23],
                *HW2 = (const float*)d_in[24], *Hb2 = (const float*)d_in[25],
                *LG2 = (const float*)d_in[26], *LB2 = (const float*)d_in[27],
                *HWo = (const float*)d_in[28], *Hbo = (const float*)d_in[29];
    float* preds = (float*)d_out;

    static bool attr_done = false;
    if (!attr_done) {
        cudaFuncSetAttribute(k_head, cudaFuncAttributeMaxDynamicSharedMemorySize,
                             SMEM_HEAD_BYTES);
        attr_done = true;
    }

    k_prep<<<1024, 256>>>(W0, b0, gg0, be0, m0, v0,
                          W1, b1, gg1, be1, m1, v1,
                          W2, b2, gg2, be2, m2, v2);
    k_hist<<<256, 256>>>(labels);
    k_scan32<<<1, 32>>>();
    k_scatter<<<256, 256>>>(labels);

    float* w1p; cudaGetSymbolAddress((void**)&w1p, g_W1p);
    float* w2p; cudaGetSymbolAddress((void**)&w2p, g_W2p);
    float* a1;  cudaGetSymbolAddress((void**)&a1,  g_alpha1);
    float* bt1; cudaGetSymbolAddress((void**)&bt1, g_beta1);
    float* a2;  cudaGetSymbolAddress((void**)&a2,  g_alpha2);
    float* bt2; cudaGetSymbolAddress((void**)&bt2, g_beta2);
    float* y1;  cudaGetSymbolAddress((void**)&y1,  g_Y1);
    float* y2;  cudaGetSymbolAddress((void**)&y2,  g_Y2);
    float* y3;  cudaGetSymbolAddress((void**)&y3,  g_Y3);

    k_gemm0<<<dim3(N0 / 128, BB / 128), 256>>>(x);
    k_gemm<<<dim3(N1 / 128, BB / 128), 256>>>(y1, w1p, a1, bt1, y2, N0, N1, 1);
    k_gemm<<<dim3(N2 / 128, BB / 128), 256>>>(y2, w2p, a2, bt2, y3, N1, N2, 0);

    k_head<<<MAX_TILES, 256, SMEM_HEAD_BYTES>>>(HW1, Hb1, LG1, LB1,
                                                HW2, Hb2, LG2, LB2,
                                                HWo, Hbo, preds);
}

// round 13
// speedup vs baseline: 1.4144x; 1.4144x over previous
#include <cuda_runtime.h>
#include <cuda_bf16.h>
#include <cstdint>
#include <cstddef>

#define EPSV 1e-5f
#define BB 32768
#define DD 1985
#define KP2 2016            // D padded to multiple of 32
#define N0 512
#define N1 256
#define N2 256
#define NE 29
#define MAX_STILES 544      // 64-sample supertiles: sum ceil(cnt/64) <= 512+28

// ----------------------- static device scratch -----------------------
__device__ __align__(128) float g_xpad[BB * KP2];
__device__ __align__(128) float g_W0p[KP2 * N0];    // [k][n]
__device__ __align__(128) float g_W1p[N0 * N1];
__device__ __align__(128) float g_W2p[N1 * N2];
__device__ float g_alpha0[N0], g_beta0[N0];
__device__ float g_alpha1[N1], g_beta1[N1];
__device__ float g_alpha2[N2], g_beta2[N2];
__device__ __align__(128) float g_Y1[BB * N0];
__device__ __align__(128) float g_Y2[BB * N1];
__device__ __align__(128) float g_Y3[BB * N2];
__device__ int g_cnt[NE], g_off[NE], g_cur[NE];
__device__ int g_idx[BB];

// ----------------------- helpers -----------------------
__device__ __forceinline__ float tf32r(float x) {
    uint32_t u;
    asm("cvt.rna.tf32.f32 %0, %1;" : "=r"(u) : "f"(x));
    return __uint_as_float(u);
}

__device__ __forceinline__ void cp16(float* s, const float* g) {
    uint32_t sa = (uint32_t)__cvta_generic_to_shared(s);
    asm volatile("cp.async.cg.shared.global [%0], [%1], 16;" :: "r"(sa), "l"(g));
}

__device__ __forceinline__ void mma_tf32(float (&d)[4], const uint32_t (&a)[4],
                                         const uint32_t (&b)[2]) {
    asm volatile(
        "mma.sync.aligned.m16n8k8.row.col.f32.tf32.tf32.f32 "
        "{%0,%1,%2,%3}, {%4,%5,%6,%7}, {%8,%9}, {%0,%1,%2,%3};"
        : "+f"(d[0]), "+f"(d[1]), "+f"(d[2]), "+f"(d[3])
        : "r"(a[0]), "r"(a[1]), "r"(a[2]), "r"(a[3]), "r"(b[0]), "r"(b[1]));
}

// ----------------------- prep: fold BN, round weights, zero counters -----------------------
__global__ void k_prep(
    const float* __restrict__ W0, const float* __restrict__ b0, const float* __restrict__ gg0,
    const float* __restrict__ be0, const float* __restrict__ m0, const float* __restrict__ v0,
    const float* __restrict__ W1, const float* __restrict__ b1, const float* __restrict__ gg1,
    const float* __restrict__ be1, const float* __restrict__ m1, const float* __restrict__ v1,
    const float* __restrict__ W2, const float* __restrict__ b2, const float* __restrict__ gg2,
    const float* __restrict__ be2, const float* __restrict__ m2, const float* __restrict__ v2)
{
    int t = blockIdx.x * blockDim.x + threadIdx.x;
    int stride = gridDim.x * blockDim.x;
    for (int i = t; i < KP2 * N0; i += stride) {
        int k = i >> 9, n = i & 511;               // N0 = 512
        g_W0p[i] = (k < DD) ? tf32r(W0[k * N0 + n]) : 0.f;
    }
    for (int i = t; i < N0 * N1; i += stride) g_W1p[i] = tf32r(W1[i]);
    for (int i = t; i < N1 * N2; i += stride) g_W2p[i] = tf32r(W2[i]);
    if (t < N0) {
        float a = gg0[t] * rsqrtf(v0[t] + EPSV);
        g_alpha0[t] = a; g_beta0[t] = (b0[t] - m0[t]) * a + be0[t];
    }
    if (t < N1) {
        float a = gg1[t] * rsqrtf(v1[t] + EPSV);
        g_alpha1[t] = a; g_beta1[t] = (b1[t] - m1[t]) * a + be1[t];
    }
    if (t < N2) {
        float a = gg2[t] * rsqrtf(v2[t] + EPSV);
        g_alpha2[t] = a; g_beta2[t] = (b2[t] - m2[t]) * a + be2[t];
    }
    if (t < NE) g_cnt[t] = 0;
}

// ----------------------- pad + tf32-round x -----------------------
__global__ void k_padx(const float* __restrict__ x) {
    int row = blockIdx.x;
    const float* src = x + (size_t)row * DD;
    float4* dst = reinterpret_cast<float4*>(g_xpad + (size_t)row * KP2);
    for (int q = threadIdx.x; q < KP2 / 4; q += blockDim.x) {
        int c = q * 4;
        float4 v;
        v.x = (c + 0 < DD) ? tf32r(src[c + 0]) : 0.f;
        v.y = (c + 1 < DD) ? tf32r(src[c + 1]) : 0.f;
        v.z = (c + 2 < DD) ? tf32r(src[c + 2]) : 0.f;
        v.w = (c + 3 < DD) ? tf32r(src[c + 3]) : 0.f;
        dst[q] = v;
    }
}

// ----------------------- label bucketing -----------------------
__global__ void k_hist(const int* __restrict__ labels) {
    __shared__ int lc[NE];
    if (threadIdx.x < NE) lc[threadIdx.x] = 0;
    __syncthreads();
    int t = blockIdx.x * blockDim.x + threadIdx.x;
    int stride = gridDim.x * blockDim.x;
    for (int i = t; i < BB; i += stride) atomicAdd(&lc[labels[i]], 1);
    __syncthreads();
    if (threadIdx.x < NE && lc[threadIdx.x]) atomicAdd(&g_cnt[threadIdx.x], lc[threadIdx.x]);
}

__global__ void k_scan32() {
    int t = threadIdx.x;
    int c = (t < NE) ? g_cnt[t] : 0;
    int x = c;
    #pragma unroll
    for (int o = 1; o < 32; o <<= 1) {
        int y = __shfl_up_sync(0xffffffffu, x, o);
        if (t >= o) x += y;
    }
    int excl = x - c;
    if (t < NE) { g_off[t] = excl; g_cur[t] = excl; }
}

__global__ void k_scatter(const int* __restrict__ labels) {
    int t = blockIdx.x * blockDim.x + threadIdx.x;
    int stride = gridDim.x * blockDim.x;
    for (int i = t; i < BB; i += stride) {
        int p = atomicAdd(&g_cur[labels[i]], 1);
        g_idx[p] = i;
    }
}

// ----------------------- GEMM0: 128x128 tile, BK=32, mma m16n8k8 tf32 -----------------------
// smem (dynamic): As[2][128*36] | Bs[2][32*136]  (strides 36/136: bank-conflict-free frags)
#define G0_AS 4608          // 128*36 floats per buffer
#define G0_BS 4352          // 32*136 floats per buffer
#define G0_SMEM ((2 * G0_AS + 2 * G0_BS) * 4)
#define G0_KB  (KP2 / 32)   // 63

__global__ void __launch_bounds__(256) k_gemm0b() {
    extern __shared__ float sm0[];
    float* Asb = sm0;
    float* Bsb = sm0 + 2 * G0_AS;

    const int tid  = threadIdx.x;
    const int lane = tid & 31, wid = tid >> 5;
    const int wm = wid & 3, wn = wid >> 2;
    const int m0 = blockIdx.y << 7, n0 = blockIdx.x << 7;

    float acc[2][8][4];
    #pragma unroll
    for (int i = 0; i < 2; i++)
        #pragma unroll
        for (int j = 0; j < 8; j++)
            #pragma unroll
            for (int q = 0; q < 4; q++) acc[i][j][q] = 0.f;

    auto load_tile = [&](int kb, int buf) {
        float* as = Asb + buf * G0_AS;
        float* bs = Bsb + buf * G0_BS;
        #pragma unroll
        for (int i = 0; i < 4; i++) {                 // A: 128 x 32 = 1024 float4
            int item = tid + i * 256;
            int row = item >> 3, c16 = item & 7;
            cp16(&as[row * 36 + c16 * 4],
                 g_xpad + (size_t)(m0 + row) * KP2 + kb * 32 + c16 * 4);
        }
        #pragma unroll
        for (int i = 0; i < 4; i++) {                 // B: 32 x 128 = 1024 float4
            int item = tid + i * 256;
            int row = item >> 5, nc = (item & 31) << 2;
            cp16(&bs[row * 136 + nc],
                 g_W0p + (size_t)(kb * 32 + row) * N0 + n0 + nc);
        }
        asm volatile("cp.async.commit_group;");
    };

    load_tile(0, 0);

    for (int kb = 0; kb < G0_KB; kb++) {
        int buf = kb & 1;
        if (kb + 1 < G0_KB) {
            load_tile(kb + 1, buf ^ 1);
            asm volatile("cp.async.wait_group 1;");
        } else {
            asm volatile("cp.async.wait_group 0;");
        }
        __syncthreads();

        const float* as = Asb + buf * G0_AS;
        const float* bs = Bsb + buf * G0_BS;
        #pragma unroll
        for (int ks = 0; ks < 4; ks++) {
            uint32_t a[2][4], b[8][2];
            const int ar = wm * 32 + (lane >> 2);
            const int ac = ks * 8 + (lane & 3);
            #pragma unroll
            for (int mt = 0; mt < 2; mt++) {
                const float* ap = &as[(ar + mt * 16) * 36 + ac];
                a[mt][0] = __float_as_uint(ap[0]);
                a[mt][1] = __float_as_uint(ap[8 * 36]);
                a[mt][2] = __float_as_uint(ap[4]);
                a[mt][3] = __float_as_uint(ap[8 * 36 + 4]);
            }
            const int br = ks * 8 + (lane & 3);
            const int bc = wn * 64 + (lane >> 2);
            #pragma unroll
            for (int nt = 0; nt < 8; nt++) {
                const float* bp = &bs[br * 136 + bc + nt * 8];
                b[nt][0] = __float_as_uint(bp[0]);
                b[nt][1] = __float_as_uint(bp[4 * 136]);
            }
            #pragma unroll
            for (int mt = 0; mt < 2; mt++)
                #pragma unroll
                for (int nt = 0; nt < 8; nt++)
                    mma_tf32(acc[mt][nt], a[mt], b[nt]);
        }
        __syncthreads();
    }

    const int rbase = m0 + wm * 32 + (lane >> 2);
    #pragma unroll
    for (int nt = 0; nt < 8; nt++) {
        int col0 = n0 + wn * 64 + nt * 8 + ((lane & 3) << 1);
        float a0 = g_alpha0[col0], a1 = g_alpha0[col0 + 1];
        float c0 = g_beta0[col0],  c1 = g_beta0[col0 + 1];
        #pragma unroll
        for (int mt = 0; mt < 2; mt++) {
            int r = rbase + mt * 16;
            g_Y1[(size_t)r * N0 + col0]           = tf32r(fmaxf(acc[mt][nt][0] * a0 + c0, 0.f));
            g_Y1[(size_t)r * N0 + col0 + 1]       = tf32r(fmaxf(acc[mt][nt][1] * a1 + c1, 0.f));
            g_Y1[(size_t)(r + 8) * N0 + col0]     = tf32r(fmaxf(acc[mt][nt][2] * a0 + c0, 0.f));
            g_Y1[(size_t)(r + 8) * N0 + col0 + 1] = tf32r(fmaxf(acc[mt][nt][3] * a1 + c1, 0.f));
        }
    }
}

// ----------------------- legacy tf32 GEMM (layers 1-2), BK=16 -----------------------
__global__ void __launch_bounds__(256) k_gemm(
    const float* __restrict__ A, const float* __restrict__ Bw,
    const float* __restrict__ al, const float* __restrict__ be,
    float* __restrict__ C, int K, int N, int rnd)
{
    __shared__ float As[2][128 * 20];
    __shared__ float Bs[2][16 * 136];

    const int tid  = threadIdx.x;
    const int lane = tid & 31, wid = tid >> 5;
    const int wm = wid & 3, wn = wid >> 2;
    const int m0 = blockIdx.y << 7, n0 = blockIdx.x << 7;
    const int KB = K >> 4;

    float acc[2][8][4];
    #pragma unroll
    for (int i = 0; i < 2; i++)
        #pragma unroll
        for (int j = 0; j < 8; j++)
            #pragma unroll
            for (int q = 0; q < 4; q++) acc[i][j][q] = 0.f;

    auto load_tile = [&](int kb, int buf) {
        #pragma unroll
        for (int i = 0; i < 2; i++) {
            int c = tid + i * 256;
            int row = c >> 2, kc = (c & 3) << 2;
            cp16(&As[buf][row * 20 + kc], A + (size_t)(m0 + row) * K + kb * 16 + kc);
        }
        #pragma unroll
        for (int i = 0; i < 2; i++) {
            int c = tid + i * 256;
            int row = c >> 5, nc = (c & 31) << 2;
            cp16(&Bs[buf][row * 136 + nc], Bw + (size_t)(kb * 16 + row) * N + n0 + nc);
        }
        asm volatile("cp.async.commit_group;");
    };

    load_tile(0, 0);

    for (int kb = 0; kb < KB; kb++) {
        int buf = kb & 1;
        if (kb + 1 < KB) {
            load_tile(kb + 1, buf ^ 1);
            asm volatile("cp.async.wait_group 1;");
        } else {
            asm volatile("cp.async.wait_group 0;");
        }
        __syncthreads();

        #pragma unroll
        for (int ks = 0; ks < 2; ks++) {
            uint32_t a[2][4], b[8][2];
            const int ar = wm * 32 + (lane >> 2);
            const int ac = ks * 8 + (lane & 3);
            #pragma unroll
            for (int mt = 0; mt < 2; mt++) {
                const float* ap = &As[buf][(ar + mt * 16) * 20 + ac];
                a[mt][0] = __float_as_uint(ap[0]);
                a[mt][1] = __float_as_uint(ap[8 * 20]);
                a[mt][2] = __float_as_uint(ap[4]);
                a[mt][3] = __float_as_uint(ap[8 * 20 + 4]);
            }
            const int br = ks * 8 + (lane & 3);
            const int bc = wn * 64 + (lane >> 2);
            #pragma unroll
            for (int nt = 0; nt < 8; nt++) {
                const float* bp = &Bs[buf][br * 136 + bc + nt * 8];
                b[nt][0] = __float_as_uint(bp[0]);
                b[nt][1] = __float_as_uint(bp[4 * 136]);
            }
            #pragma unroll
            for (int mt = 0; mt < 2; mt++)
                #pragma unroll
                for (int nt = 0; nt < 8; nt++)
                    mma_tf32(acc[mt][nt], a[mt], b[nt]);
        }
        __syncthreads();
    }

    const int rbase = m0 + wm * 32 + (lane >> 2);
    #pragma unroll
    for (int nt = 0; nt < 8; nt++) {
        int col0 = n0 + wn * 64 + nt * 8 + ((lane & 3) << 1);
        float a0 = al[col0], a1 = al[col0 + 1];
        float c0 = be[col0], c1 = be[col0 + 1];
        #pragma unroll
        for (int mt = 0; mt < 2; mt++) {
            int r = rbase + mt * 16;
            float v0 = fmaxf(acc[mt][nt][0] * a0 + c0, 0.f);
            float v1 = fmaxf(acc[mt][nt][1] * a1 + c1, 0.f);
            float v2 = fmaxf(acc[mt][nt][2] * a0 + c0, 0.f);
            float v3 = fmaxf(acc[mt][nt][3] * a1 + c1, 0.f);
            if (rnd) { v0 = tf32r(v0); v1 = tf32r(v1); v2 = tf32r(v2); v3 = tf32r(v3); }
            C[(size_t)r * N + col0]           = v0;
            C[(size_t)r * N + col0 + 1]       = v1;
            C[(size_t)(r + 8) * N + col0]     = v2;
            C[(size_t)(r + 8) * N + col0 + 1] = v3;
        }
    }
}

// ----------------------- fused per-expert head (64-sample supertile = 2 subtiles) ------------
#define OFF_HW1 0
#define OFF_HW2 32768
#define OFF_FT  40960
#define OFF_H1  49280
#define OFF_P   53504
#define SMEM_HEAD_FLOATS (OFF_P + 641)
#define SMEM_HEAD_BYTES  (SMEM_HEAD_FLOATS * 4)

__global__ void __launch_bounds__(256) k_head(
    const float* __restrict__ HW1, const float* __restrict__ Hb1,
    const float* __restrict__ LG1, const float* __restrict__ LB1,
    const float* __restrict__ HW2, const float* __restrict__ Hb2,
    const float* __restrict__ LG2, const float* __restrict__ LB2,
    const float* __restrict__ HWo, const float* __restrict__ Hbo,
    float* __restrict__ preds)
{
    extern __shared__ float sm[];
    const int bid = blockIdx.x;
    const int tid = threadIdx.x;

    __shared__ int s_e, s_s0, s_cnt;
    if (tid == 0) {
        int off = 0, tacc = 0, e = -1, s0 = 0, cnt = 0;
        #pragma unroll 1
        for (int i = 0; i < NE; i++) {
            int c = g_cnt[i];
            int nt = (c + 63) >> 6;                 // 64-sample supertiles
            if (bid < tacc + nt) {
                e = i;
                int j = bid - tacc;
                s0 = off + j * 64;
                int rem = c - j * 64;
                cnt = rem < 64 ? rem : 64;
                break;
            }
            tacc += nt; off += c;
        }
        s_e = e; s_s0 = s0; s_cnt = cnt;
    }
    __syncthreads();
    if (s_e < 0) return;
    const int e = s_e;

    float* LG1s = sm + OFF_P;
    float* LB1s = LG1s + 128;
    float* Hb1s = LB1s + 128;
    float* LG2s = Hb1s + 128;
    float* LB2s = LG2s + 64;
    float* Hb2s = LB2s + 64;
    float* HWos = Hb2s + 64;

    {   // expert weights + params, loaded ONCE per supertile
        const float4* s1 = reinterpret_cast<const float4*>(HW1 + (size_t)e * 256 * 128);
        float4* d1 = reinterpret_cast<float4*>(sm + OFF_HW1);
        for (int c = tid; c < 8192; c += 256) d1[c] = s1[c];
        const float4* s2 = reinterpret_cast<const float4*>(HW2 + (size_t)e * 128 * 64);
        float4* d2 = reinterpret_cast<float4*>(sm + OFF_HW2);
        for (int c = tid; c < 2048; c += 256) d2[c] = s2[c];
        if (tid < 128) {
            LG1s[tid] = LG1[e * 128 + tid];
            LB1s[tid] = LB1[e * 128 + tid];
            Hb1s[tid] = Hb1[e * 128 + tid];
        }
        if (tid < 64) {
            LG2s[tid] = LG2[e * 64 + tid];
            LB2s[tid] = LB2[e * 64 + tid];
            Hb2s[tid] = Hb2[e * 64 + tid];
            HWos[tid] = HWo[e * 64 + tid];
        }
    }

    float hbo = Hbo[e];

    #pragma unroll 1
    for (int st = 0; st < 2; st++) {
        int scnt = s_cnt - st * 32;
        if (scnt <= 0) break;
        if (scnt > 32) scnt = 32;
        const int s0s = s_s0 + st * 32;

        // feats subtile
        for (int c = tid; c < 32 * 64; c += 256) {
            int s = c >> 6, q = c & 63;
            float4 v = make_float4(0.f, 0.f, 0.f, 0.f);
            if (s < scnt)
                v = reinterpret_cast<const float4*>(g_Y3 + (size_t)g_idx[s0s + s] * 256)[q];
            reinterpret_cast<float4*>(sm + OFF_FT + s * 260)[q] = v;
        }
        __syncthreads();

        // layer 1: h1 = relu(LN(ft @ HW1 + Hb1))  [32 x 128]
        {
            const int hq = tid & 31;
            const int sg = tid >> 5;
            float acc1[4][4];
            #pragma unroll
            for (int i = 0; i < 4; i++)
                #pragma unroll
                for (int j = 0; j < 4; j++) acc1[i][j] = Hb1s[hq * 4 + j];

            const float4* w4 = reinterpret_cast<const float4*>(sm + OFF_HW1);
            const float* ftb = sm + OFF_FT + sg * 4 * 260;
            #pragma unroll 4
            for (int k = 0; k < 256; k++) {
                float4 w = w4[k * 32 + hq];
                #pragma unroll
                for (int i = 0; i < 4; i++) {
                    float f = ftb[i * 260 + k];
                    acc1[i][0] += f * w.x;
                    acc1[i][1] += f * w.y;
                    acc1[i][2] += f * w.z;
                    acc1[i][3] += f * w.w;
                }
            }
            #pragma unroll
            for (int i = 0; i < 4; i++) {
                float s1 = acc1[i][0] + acc1[i][1] + acc1[i][2] + acc1[i][3];
                float s2 = acc1[i][0] * acc1[i][0] + acc1[i][1] * acc1[i][1]
                         + acc1[i][2] * acc1[i][2] + acc1[i][3] * acc1[i][3];
                #pragma unroll
                for (int o = 16; o > 0; o >>= 1) {
                    s1 += __shfl_xor_sync(0xffffffffu, s1, o);
                    s2 += __shfl_xor_sync(0xffffffffu, s2, o);
                }
                float mu  = s1 * (1.f / 128.f);
                float inv = rsqrtf(s2 * (1.f / 128.f) - mu * mu + EPSV);
                float4 o4;
                o4.x = fmaxf((acc1[i][0] - mu) * inv * LG1s[hq * 4 + 0] + LB1s[hq * 4 + 0], 0.f);
                o4.y = fmaxf((acc1[i][1] - mu) * inv * LG1s[hq * 4 + 1] + LB1s[hq * 4 + 1], 0.f);
                o4.z = fmaxf((acc1[i][2] - mu) * inv * LG1s[hq * 4 + 2] + LB1s[hq * 4 + 2], 0.f);
                o4.w = fmaxf((acc1[i][3] - mu) * inv * LG1s[hq * 4 + 3] + LB1s[hq * 4 + 3], 0.f);
                *reinterpret_cast<float4*>(sm + OFF_H1 + (sg * 4 + i) * 132 + hq * 4) = o4;
            }
        }
        __syncthreads();

        // layer 2 + output
        {
            const int kq  = tid & 15;
            const int sg2 = tid >> 4;
            float acc2[2][4];
            #pragma unroll
            for (int i = 0; i < 2; i++)
                #pragma unroll
                for (int j = 0; j < 4; j++) acc2[i][j] = Hb2s[kq * 4 + j];

            const float4* w4 = reinterpret_cast<const float4*>(sm + OFF_HW2);
            const float* h1b = sm + OFF_H1 + sg2 * 2 * 132;
            #pragma unroll 4
            for (int h = 0; h < 128; h++) {
                float4 w = w4[h * 16 + kq];
                #pragma unroll
                for (int i = 0; i < 2; i++) {
                    float f = h1b[i * 132 + h];
                    acc2[i][0] += f * w.x;
                    acc2[i][1] += f * w.y;
                    acc2[i][2] += f * w.z;
                    acc2[i][3] += f * w.w;
                }
            }
            #pragma unroll
            for (int i = 0; i < 2; i++) {
                float s1 = acc2[i][0] + acc2[i][1] + acc2[i][2] + acc2[i][3];
                float s2 = acc2[i][0] * acc2[i][0] + acc2[i][1] * acc2[i][1]
                         + acc2[i][2] * acc2[i][2] + acc2[i][3] * acc2[i][3];
                #pragma unroll
                for (int o = 8; o > 0; o >>= 1) {
                    s1 += __shfl_xor_sync(0xffffffffu, s1, o);
                    s2 += __shfl_xor_sync(0xffffffffu, s2, o);
                }
                float mu  = s1 * (1.f / 64.f);
                float inv = rsqrtf(s2 * (1.f / 64.f) - mu * mu + EPSV);
                float partial = 0.f;
                #pragma unroll
                for (int j = 0; j < 4; j++) {
                    float v = fmaxf((acc2[i][j] - mu) * inv * LG2s[kq * 4 + j] + LB2s[kq * 4 + j], 0.f);
                    partial += v * HWos[kq * 4 + j];
                }
                #pragma unroll
                for (int o = 8; o > 0; o >>= 1)
                    partial += __shfl_xor_sync(0xffffffffu, partial, o);
                if (kq == 0) {
                    int s = sg2 * 2 + i;
                    if (s < scnt) preds[g_idx[s0s + s]] = partial + hbo;
                }
            }
        }
        __syncthreads();   // h1/ft safe to overwrite next subtile
    }
}

// ----------------------- launch -----------------------
extern "C" void kernel_launch(void* const* d_in, const int* in_sizes, int n_in,
                              void* d_out, int out_size) {
    const float* x      = (const float*)d_in[0];
    const int*   labels = (const int*)  d_in[1];
    const float *W0 = (const float*)d_in[2],  *b0 = (const float*)d_in[3],
                *gg0 = (const float*)d_in[4], *be0 = (const float*)d_in[5],
                *m0 = (const float*)d_in[6],  *v0 = (const float*)d_in[7];
    const float *W1 = (const float*)d_in[8],  *b1 = (const float*)d_in[9],
                *gg1 = (const float*)d_in[10], *be1 = (const float*)d_in[11],
                *m1 = (const float*)d_in[12], *v1 = (const float*)d_in[13];
    const float *W2 = (const float*)d_in[14], *b2 = (const float*)d_in[15],
                *gg2 = (const float*)d_in[16], *be2 = (const float*)d_in[17],
                *m2 = (const float*)d_in[18], *v2 = (const float*)d_in[19];
    const float *HW1 = (const float*)d_in[20], *Hb1 = (const float*)d_in[21],
                *LG1 = (const float*)d_in[22], *LB1 = (const float*)d_in[23],
                *HW2 = (const float*)d_in[24], *Hb2 = (const float*)d_in[25],
                *LG2 = (const float*)d_in[26], *LB2 = (const float*)d_in[27],
                *HWo = (const float*)d_in[28], *Hbo = (const float*)d_in[29];
    float* preds = (float*)d_out;

    static bool attr_done = false;
    if (!attr_done) {
        cudaFuncSetAttribute(k_head, cudaFuncAttributeMaxDynamicSharedMemorySize,
                             SMEM_HEAD_BYTES);
        cudaFuncSetAttribute(k_gemm0b, cudaFuncAttributeMaxDynamicSharedMemorySize,
                             G0_SMEM);
        attr_done = true;
    }

    float* w1p; cudaGetSymbolAddress((void**)&w1p, g_W1p);
    float* w2p; cudaGetSymbolAddress((void**)&w2p, g_W2p);
    float* a1;  cudaGetSymbolAddress((void**)&a1,  g_alpha1);
    float* bt1; cudaGetSymbolAddress((void**)&bt1, g_beta1);
    float* a2;  cudaGetSymbolAddress((void**)&a2,  g_alpha2);
    float* bt2; cudaGetSymbolAddress((void**)&bt2, g_beta2);
    float* y1;  cudaGetSymbolAddress((void**)&y1,  g_Y1);
    float* y2;  cudaGetSymbolAddress((void**)&y2,  g_Y2);
    float* y3;  cudaGetSymbolAddress((void**)&y3,  g_Y3);

    // order chosen so GEMM0 is launch index 3 (the one ncu captures)
    k_prep<<<1024, 256>>>(W0, b0, gg0, be0, m0, v0,
                          W1, b1, gg1, be1, m1, v1,
                          W2, b2, gg2, be2, m2, v2);
    k_padx<<<BB, 256>>>(x);
    k_hist<<<256, 256>>>(labels);
    k_gemm0b<<<dim3(N0 / 128, BB / 128), 256, G0_SMEM>>>();
    k_gemm<<<dim3(N1 / 128, BB / 128), 256>>>(y1, w1p, a1, bt1, y2, N0, N1, 1);
    k_gemm<<<dim3(N2 / 128, BB / 128), 256>>>(y2, w2p, a2, bt2, y3, N1, N2, 0);
    k_scan32<<<1, 32>>>();
    k_scatter<<<256, 256>>>(labels);
    k_head<<<MAX_STILES, 256, SMEM_HEAD_BYTES>>>(HW1, Hb1, LG1, LB1,
                                                 HW2, Hb2, LG2, LB2,
                                                 HWo, Hbo, preds);
}

// round 14
// speedup vs baseline: 1.4154x; 1.0007x over previous
#include <cuda_runtime.h>
#include <cuda_bf16.h>
#include <cstdint>
#include <cstddef>

#define EPSV 1e-5f
#define BB 32768
#define DD 1985
#define KP2 2016            // D padded to multiple of 32
#define N0 512
#define N1 256
#define N2 256
#define NE 29
#define MAX_STILES 544      // 64-sample supertiles: sum ceil(cnt/64) <= 512+28

// ----------------------- static device scratch -----------------------
__device__ __align__(128) float g_xpad[BB * KP2];
__device__ __align__(128) float g_W0p[KP2 * N0];    // [k][n]
__device__ __align__(128) float g_W1p[N0 * N1];
__device__ __align__(128) float g_W2p[N1 * N2];
__device__ float g_alpha0[N0], g_beta0[N0];
__device__ float g_alpha1[N1], g_beta1[N1];
__device__ float g_alpha2[N2], g_beta2[N2];
__device__ __align__(128) float g_Y1[BB * N0];
__device__ __align__(128) float g_Y2[BB * N1];
__device__ __align__(128) float g_Y3[BB * N2];
__device__ int g_cnt[NE], g_off[NE], g_cur[NE];
__device__ int g_idx[BB];

// ----------------------- helpers -----------------------
__device__ __forceinline__ float tf32r(float x) {
    uint32_t u;
    asm("cvt.rna.tf32.f32 %0, %1;" : "=r"(u) : "f"(x));
    return __uint_as_float(u);
}

__device__ __forceinline__ void cp16(float* s, const float* g) {
    uint32_t sa = (uint32_t)__cvta_generic_to_shared(s);
    asm volatile("cp.async.cg.shared.global [%0], [%1], 16;" :: "r"(sa), "l"(g));
}

__device__ __forceinline__ void mma_tf32(float (&d)[4], const uint32_t (&a)[4],
                                         const uint32_t (&b)[2]) {
    asm volatile(
        "mma.sync.aligned.m16n8k8.row.col.f32.tf32.tf32.f32 "
        "{%0,%1,%2,%3}, {%4,%5,%6,%7}, {%8,%9}, {%0,%1,%2,%3};"
        : "+f"(d[0]), "+f"(d[1]), "+f"(d[2]), "+f"(d[3])
        : "r"(a[0]), "r"(a[1]), "r"(a[2]), "r"(a[3]), "r"(b[0]), "r"(b[1]));
}

// ----------------------- prep: fold BN, round weights, zero counters -----------------------
__global__ void k_prep(
    const float* __restrict__ W0, const float* __restrict__ b0, const float* __restrict__ gg0,
    const float* __restrict__ be0, const float* __restrict__ m0, const float* __restrict__ v0,
    const float* __restrict__ W1, const float* __restrict__ b1, const float* __restrict__ gg1,
    const float* __restrict__ be1, const float* __restrict__ m1, const float* __restrict__ v1,
    const float* __restrict__ W2, const float* __restrict__ b2, const float* __restrict__ gg2,
    const float* __restrict__ be2, const float* __restrict__ m2, const float* __restrict__ v2)
{
    int t = blockIdx.x * blockDim.x + threadIdx.x;
    int stride = gridDim.x * blockDim.x;
    for (int i = t; i < KP2 * N0; i += stride) {
        int k = i >> 9, n = i & 511;               // N0 = 512
        g_W0p[i] = (k < DD) ? tf32r(W0[k * N0 + n]) : 0.f;
    }
    for (int i = t; i < N0 * N1; i += stride) g_W1p[i] = tf32r(W1[i]);
    for (int i = t; i < N1 * N2; i += stride) g_W2p[i] = tf32r(W2[i]);
    if (t < N0) {
        float a = gg0[t] * rsqrtf(v0[t] + EPSV);
        g_alpha0[t] = a; g_beta0[t] = (b0[t] - m0[t]) * a + be0[t];
    }
    if (t < N1) {
        float a = gg1[t] * rsqrtf(v1[t] + EPSV);
        g_alpha1[t] = a; g_beta1[t] = (b1[t] - m1[t]) * a + be1[t];
    }
    if (t < N2) {
        float a = gg2[t] * rsqrtf(v2[t] + EPSV);
        g_alpha2[t] = a; g_beta2[t] = (b2[t] - m2[t]) * a + be2[t];
    }
    if (t < NE) g_cnt[t] = 0;
}

// ----------------------- pad + tf32-round x -----------------------
__global__ void k_padx(const float* __restrict__ x) {
    int row = blockIdx.x;
    const float* src = x + (size_t)row * DD;
    float4* dst = reinterpret_cast<float4*>(g_xpad + (size_t)row * KP2);
    for (int q = threadIdx.x; q < KP2 / 4; q += blockDim.x) {
        int c = q * 4;
        float4 v;
        v.x = (c + 0 < DD) ? tf32r(src[c + 0]) : 0.f;
        v.y = (c + 1 < DD) ? tf32r(src[c + 1]) : 0.f;
        v.z = (c + 2 < DD) ? tf32r(src[c + 2]) : 0.f;
        v.w = (c + 3 < DD) ? tf32r(src[c + 3]) : 0.f;
        dst[q] = v;
    }
}

// ----------------------- label bucketing -----------------------
__global__ void k_hist(const int* __restrict__ labels) {
    __shared__ int lc[NE];
    if (threadIdx.x < NE) lc[threadIdx.x] = 0;
    __syncthreads();
    int t = blockIdx.x * blockDim.x + threadIdx.x;
    int stride = gridDim.x * blockDim.x;
    for (int i = t; i < BB; i += stride) atomicAdd(&lc[labels[i]], 1);
    __syncthreads();
    if (threadIdx.x < NE && lc[threadIdx.x]) atomicAdd(&g_cnt[threadIdx.x], lc[threadIdx.x]);
}

__global__ void k_scan32() {
    int t = threadIdx.x;
    int c = (t < NE) ? g_cnt[t] : 0;
    int x = c;
    #pragma unroll
    for (int o = 1; o < 32; o <<= 1) {
        int y = __shfl_up_sync(0xffffffffu, x, o);
        if (t >= o) x += y;
    }
    int excl = x - c;
    if (t < NE) { g_off[t] = excl; g_cur[t] = excl; }
}

__global__ void k_scatter(const int* __restrict__ labels) {
    int t = blockIdx.x * blockDim.x + threadIdx.x;
    int stride = gridDim.x * blockDim.x;
    for (int i = t; i < BB; i += stride) {
        int p = atomicAdd(&g_cur[labels[i]], 1);
        g_idx[p] = i;
    }
}

// ----------------------- GEMM0: 128x128 tile, BK=32, mma m16n8k8 tf32 -----------------------
// smem (dynamic): As[2][128*36] | Bs[2][32*136]  (strides 36/136: bank-conflict-free frags)
#define G0_AS 4608          // 128*36 floats per buffer
#define G0_BS 4352          // 32*136 floats per buffer
#define G0_SMEM ((2 * G0_AS + 2 * G0_BS) * 4)
#define G0_KB  (KP2 / 32)   // 63

__global__ void __launch_bounds__(256) k_gemm0b() {
    extern __shared__ float sm0[];
    float* Asb = sm0;
    float* Bsb = sm0 + 2 * G0_AS;

    const int tid  = threadIdx.x;
    const int lane = tid & 31, wid = tid >> 5;
    const int wm = wid & 3, wn = wid >> 2;
    const int m0 = blockIdx.y << 7, n0 = blockIdx.x << 7;

    float acc[2][8][4];
    #pragma unroll
    for (int i = 0; i < 2; i++)
        #pragma unroll
        for (int j = 0; j < 8; j++)
            #pragma unroll
            for (int q = 0; q < 4; q++) acc[i][j][q] = 0.f;

    auto load_tile = [&](int kb, int buf) {
        float* as = Asb + buf * G0_AS;
        float* bs = Bsb + buf * G0_BS;
        #pragma unroll
        for (int i = 0; i < 4; i++) {                 // A: 128 x 32 = 1024 float4
            int item = tid + i * 256;
            int row = item >> 3, c16 = item & 7;
            cp16(&as[row * 36 + c16 * 4],
                 g_xpad + (size_t)(m0 + row) * KP2 + kb * 32 + c16 * 4);
        }
        #pragma unroll
        for (int i = 0; i < 4; i++) {                 // B: 32 x 128 = 1024 float4
            int item = tid + i * 256;
            int row = item >> 5, nc = (item & 31) << 2;
            cp16(&bs[row * 136 + nc],
                 g_W0p + (size_t)(kb * 32 + row) * N0 + n0 + nc);
        }
        asm volatile("cp.async.commit_group;");
    };

    load_tile(0, 0);

    for (int kb = 0; kb < G0_KB; kb++) {
        int buf = kb & 1;
        if (kb + 1 < G0_KB) {
            load_tile(kb + 1, buf ^ 1);
            asm volatile("cp.async.wait_group 1;");
        } else {
            asm volatile("cp.async.wait_group 0;");
        }
        __syncthreads();

        const float* as = Asb + buf * G0_AS;
        const float* bs = Bsb + buf * G0_BS;
        #pragma unroll
        for (int ks = 0; ks < 4; ks++) {
            uint32_t a[2][4], b[8][2];
            const int ar = wm * 32 + (lane >> 2);
            const int ac = ks * 8 + (lane & 3);
            #pragma unroll
            for (int mt = 0; mt < 2; mt++) {
                const float* ap = &as[(ar + mt * 16) * 36 + ac];
                a[mt][0] = __float_as_uint(ap[0]);
                a[mt][1] = __float_as_uint(ap[8 * 36]);
                a[mt][2] = __float_as_uint(ap[4]);
                a[mt][3] = __float_as_uint(ap[8 * 36 + 4]);
            }
            const int br = ks * 8 + (lane & 3);
            const int bc = wn * 64 + (lane >> 2);
            #pragma unroll
            for (int nt = 0; nt < 8; nt++) {
                const float* bp = &bs[br * 136 + bc + nt * 8];
                b[nt][0] = __float_as_uint(bp[0]);
                b[nt][1] = __float_as_uint(bp[4 * 136]);
            }
            #pragma unroll
            for (int mt = 0; mt < 2; mt++)
                #pragma unroll
                for (int nt = 0; nt < 8; nt++)
                    mma_tf32(acc[mt][nt], a[mt], b[nt]);
        }
        __syncthreads();
    }

    const int rbase = m0 + wm * 32 + (lane >> 2);
    #pragma unroll
    for (int nt = 0; nt < 8; nt++) {
        int col0 = n0 + wn * 64 + nt * 8 + ((lane & 3) << 1);
        float a0 = g_alpha0[col0], a1 = g_alpha0[col0 + 1];
        float c0 = g_beta0[col0],  c1 = g_beta0[col0 + 1];
        #pragma unroll
        for (int mt = 0; mt < 2; mt++) {
            int r = rbase + mt * 16;
            g_Y1[(size_t)r * N0 + col0]           = tf32r(fmaxf(acc[mt][nt][0] * a0 + c0, 0.f));
            g_Y1[(size_t)r * N0 + col0 + 1]       = tf32r(fmaxf(acc[mt][nt][1] * a1 + c1, 0.f));
            g_Y1[(size_t)(r + 8) * N0 + col0]     = tf32r(fmaxf(acc[mt][nt][2] * a0 + c0, 0.f));
            g_Y1[(size_t)(r + 8) * N0 + col0 + 1] = tf32r(fmaxf(acc[mt][nt][3] * a1 + c1, 0.f));
        }
    }
}

// ----------------------- legacy tf32 GEMM (layers 1-2), BK=16 -----------------------
__global__ void __launch_bounds__(256) k_gemm(
    const float* __restrict__ A, const float* __restrict__ Bw,
    const float* __restrict__ al, const float* __restrict__ be,
    float* __restrict__ C, int K, int N, int rnd)
{
    __shared__ float As[2][128 * 20];
    __shared__ float Bs[2][16 * 136];

    const int tid  = threadIdx.x;
    const int lane = tid & 31, wid = tid >> 5;
    const int wm = wid & 3, wn = wid >> 2;
    const int m0 = blockIdx.y << 7, n0 = blockIdx.x << 7;
    const int KB = K >> 4;

    float acc[2][8][4];
    #pragma unroll
    for (int i = 0; i < 2; i++)
        #pragma unroll
        for (int j = 0; j < 8; j++)
            #pragma unroll
            for (int q = 0; q < 4; q++) acc[i][j][q] = 0.f;

    auto load_tile = [&](int kb, int buf) {
        #pragma unroll
        for (int i = 0; i < 2; i++) {
            int c = tid + i * 256;
            int row = c >> 2, kc = (c & 3) << 2;
            cp16(&As[buf][row * 20 + kc], A + (size_t)(m0 + row) * K + kb * 16 + kc);
        }
        #pragma unroll
        for (int i = 0; i < 2; i++) {
            int c = tid + i * 256;
            int row = c >> 5, nc = (c & 31) << 2;
            cp16(&Bs[buf][row * 136 + nc], Bw + (size_t)(kb * 16 + row) * N + n0 + nc);
        }
        asm volatile("cp.async.commit_group;");
    };

    load_tile(0, 0);

    for (int kb = 0; kb < KB; kb++) {
        int buf = kb & 1;
        if (kb + 1 < KB) {
            load_tile(kb + 1, buf ^ 1);
            asm volatile("cp.async.wait_group 1;");
        } else {
            asm volatile("cp.async.wait_group 0;");
        }
        __syncthreads();

        #pragma unroll
        for (int ks = 0; ks < 2; ks++) {
            uint32_t a[2][4], b[8][2];
            const int ar = wm * 32 + (lane >> 2);
            const int ac = ks * 8 + (lane & 3);
            #pragma unroll
            for (int mt = 0; mt < 2; mt++) {
                const float* ap = &As[buf][(ar + mt * 16) * 20 + ac];
                a[mt][0] = __float_as_uint(ap[0]);
                a[mt][1] = __float_as_uint(ap[8 * 20]);
                a[mt][2] = __float_as_uint(ap[4]);
                a[mt][3] = __float_as_uint(ap[8 * 20 + 4]);
            }
            const int br = ks * 8 + (lane & 3);
            const int bc = wn * 64 + (lane >> 2);
            #pragma unroll
            for (int nt = 0; nt < 8; nt++) {
                const float* bp = &Bs[buf][br * 136 + bc + nt * 8];
                b[nt][0] = __float_as_uint(bp[0]);
                b[nt][1] = __float_as_uint(bp[4 * 136]);
            }
            #pragma unroll
            for (int mt = 0; mt < 2; mt++)
                #pragma unroll
                for (int nt = 0; nt < 8; nt++)
                    mma_tf32(acc[mt][nt], a[mt], b[nt]);
        }
        __syncthreads();
    }

    const int rbase = m0 + wm * 32 + (lane >> 2);
    #pragma unroll
    for (int nt = 0; nt < 8; nt++) {
        int col0 = n0 + wn * 64 + nt * 8 + ((lane & 3) << 1);
        float a0 = al[col0], a1 = al[col0 + 1];
        float c0 = be[col0], c1 = be[col0 + 1];
        #pragma unroll
        for (int mt = 0; mt < 2; mt++) {
            int r = rbase + mt * 16;
            float v0 = fmaxf(acc[mt][nt][0] * a0 + c0, 0.f);
            float v1 = fmaxf(acc[mt][nt][1] * a1 + c1, 0.f);
            float v2 = fmaxf(acc[mt][nt][2] * a0 + c0, 0.f);
            float v3 = fmaxf(acc[mt][nt][3] * a1 + c1, 0.f);
            if (rnd) { v0 = tf32r(v0); v1 = tf32r(v1); v2 = tf32r(v2); v3 = tf32r(v3); }
            C[(size_t)r * N + col0]           = v0;
            C[(size_t)r * N + col0 + 1]       = v1;
            C[(size_t)(r + 8) * N + col0]     = v2;
            C[(size_t)(r + 8) * N + col0 + 1] = v3;
        }
    }
}

// ----------------------- fused per-expert head (64-sample supertile = 2 subtiles) ------------
#define OFF_HW1 0
#define OFF_HW2 32768
#define OFF_FT  40960
#define OFF_H1  49280
#define OFF_P   53504
#define SMEM_HEAD_FLOATS (OFF_P + 641)
#define SMEM_HEAD_BYTES  (SMEM_HEAD_FLOATS * 4)

__global__ void __launch_bounds__(256) k_head(
    const float* __restrict__ HW1, const float* __restrict__ Hb1,
    const float* __restrict__ LG1, const float* __restrict__ LB1,
    const float* __restrict__ HW2, const float* __restrict__ Hb2,
    const float* __restrict__ LG2, const float* __restrict__ LB2,
    const float* __restrict__ HWo, const float* __restrict__ Hbo,
    float* __restrict__ preds)
{
    extern __shared__ float sm[];
    const int bid = blockIdx.x;
    const int tid = threadIdx.x;

    __shared__ int s_e, s_s0, s_cnt;
    if (tid == 0) {
        int off = 0, tacc = 0, e = -1, s0 = 0, cnt = 0;
        #pragma unroll 1
        for (int i = 0; i < NE; i++) {
            int c = g_cnt[i];
            int nt = (c + 63) >> 6;                 // 64-sample supertiles
            if (bid < tacc + nt) {
                e = i;
                int j = bid - tacc;
                s0 = off + j * 64;
                int rem = c - j * 64;
                cnt = rem < 64 ? rem : 64;
                break;
            }
            tacc += nt; off += c;
        }
        s_e = e; s_s0 = s0; s_cnt = cnt;
    }
    __syncthreads();
    if (s_e < 0) return;
    const int e = s_e;

    float* LG1s = sm + OFF_P;
    float* LB1s = LG1s + 128;
    float* Hb1s = LB1s + 128;
    float* LG2s = Hb1s + 128;
    float* LB2s = LG2s + 64;
    float* Hb2s = LB2s + 64;
    float* HWos = Hb2s + 64;

    {   // expert weights + params, loaded ONCE per supertile
        const float4* s1 = reinterpret_cast<const float4*>(HW1 + (size_t)e * 256 * 128);
        float4* d1 = reinterpret_cast<float4*>(sm + OFF_HW1);
        for (int c = tid; c < 8192; c += 256) d1[c] = s1[c];
        const float4* s2 = reinterpret_cast<const float4*>(HW2 + (size_t)e * 128 * 64);
        float4* d2 = reinterpret_cast<float4*>(sm + OFF_HW2);
        for (int c = tid; c < 2048; c += 256) d2[c] = s2[c];
        if (tid < 128) {
            LG1s[tid] = LG1[e * 128 + tid];
            LB1s[tid] = LB1[e * 128 + tid];
            Hb1s[tid] = Hb1[e * 128 + tid];
        }
        if (tid < 64) {
            LG2s[tid] = LG2[e * 64 + tid];
            LB2s[tid] = LB2[e * 64 + tid];
            Hb2s[tid] = Hb2[e * 64 + tid];
            HWos[tid] = HWo[e * 64 + tid];
        }
    }

    float hbo = Hbo[e];

    #pragma unroll 1
    for (int st = 0; st < 2; st++) {
        int scnt = s_cnt - st * 32;
        if (scnt <= 0) break;
        if (scnt > 32) scnt = 32;
        const int s0s = s_s0 + st * 32;

        // feats subtile
        for (int c = tid; c < 32 * 64; c += 256) {
            int s = c >> 6, q = c & 63;
            float4 v = make_float4(0.f, 0.f, 0.f, 0.f);
            if (s < scnt)
                v = reinterpret_cast<const float4*>(g_Y3 + (size_t)g_idx[s0s + s] * 256)[q];
            reinterpret_cast<float4*>(sm + OFF_FT + s * 260)[q] = v;
        }
        __syncthreads();

        // layer 1: h1 = relu(LN(ft @ HW1 + Hb1))  [32 x 128]
        {
            const int hq = tid & 31;
            const int sg = tid >> 5;
            float acc1[4][4];
            #pragma unroll
            for (int i = 0; i < 4; i++)
                #pragma unroll
                for (int j = 0; j < 4; j++) acc1[i][j] = Hb1s[hq * 4 + j];

            const float4* w4 = reinterpret_cast<const float4*>(sm + OFF_HW1);
            const float* ftb = sm + OFF_FT + sg * 4 * 260;
            #pragma unroll 4
            for (int k = 0; k < 256; k++) {
                float4 w = w4[k * 32 + hq];
                #pragma unroll
                for (int i = 0; i < 4; i++) {
                    float f = ftb[i * 260 + k];
                    acc1[i][0] += f * w.x;
                    acc1[i][1] += f * w.y;
                    acc1[i][2] += f * w.z;
                    acc1[i][3] += f * w.w;
                }
            }
            #pragma unroll
            for (int i = 0; i < 4; i++) {
                float s1 = acc1[i][0] + acc1[i][1] + acc1[i][2] + acc1[i][3];
                float s2 = acc1[i][0] * acc1[i][0] + acc1[i][1] * acc1[i][1]
                         + acc1[i][2] * acc1[i][2] + acc1[i][3] * acc1[i][3];
                #pragma unroll
                for (int o = 16; o > 0; o >>= 1) {
                    s1 += __shfl_xor_sync(0xffffffffu, s1, o);
                    s2 += __shfl_xor_sync(0xffffffffu, s2, o);
                }
                float mu  = s1 * (1.f / 128.f);
                float inv = rsqrtf(s2 * (1.f / 128.f) - mu * mu + EPSV);
                float4 o4;
                o4.x = fmaxf((acc1[i][0] - mu) * inv * LG1s[hq * 4 + 0] + LB1s[hq * 4 + 0], 0.f);
                o4.y = fmaxf((acc1[i][1] - mu) * inv * LG1s[hq * 4 + 1] + LB1s[hq * 4 + 1], 0.f);
                o4.z = fmaxf((acc1[i][2] - mu) * inv * LG1s[hq * 4 + 2] + LB1s[hq * 4 + 2], 0.f);
                o4.w = fmaxf((acc1[i][3] - mu) * inv * LG1s[hq * 4 + 3] + LB1s[hq * 4 + 3], 0.f);
                *reinterpret_cast<float4*>(sm + OFF_H1 + (sg * 4 + i) * 132 + hq * 4) = o4;
            }
        }
        __syncthreads();

        // layer 2 + output
        {
            const int kq  = tid & 15;
            const int sg2 = tid >> 4;
            float acc2[2][4];
            #pragma unroll
            for (int i = 0; i < 2; i++)
                #pragma unroll
                for (int j = 0; j < 4; j++) acc2[i][j] = Hb2s[kq * 4 + j];

            const float4* w4 = reinterpret_cast<const float4*>(sm + OFF_HW2);
            const float* h1b = sm + OFF_H1 + sg2 * 2 * 132;
            #pragma unroll 4
            for (int h = 0; h < 128; h++) {
                float4 w = w4[h * 16 + kq];
                #pragma unroll
                for (int i = 0; i < 2; i++) {
                    float f = h1b[i * 132 + h];
                    acc2[i][0] += f * w.x;
                    acc2[i][1] += f * w.y;
                    acc2[i][2] += f * w.z;
                    acc2[i][3] += f * w.w;
                }
            }
            #pragma unroll
            for (int i = 0; i < 2; i++) {
                float s1 = acc2[i][0] + acc2[i][1] + acc2[i][2] + acc2[i][3];
                float s2 = acc2[i][0] * acc2[i][0] + acc2[i][1] * acc2[i][1]
                         + acc2[i][2] * acc2[i][2] + acc2[i][3] * acc2[i][3];
                #pragma unroll
                for (int o = 8; o > 0; o >>= 1) {
                    s1 += __shfl_xor_sync(0xffffffffu, s1, o);
                    s2 += __shfl_xor_sync(0xffffffffu, s2, o);
                }
                float mu  = s1 * (1.f / 64.f);
                float inv = rsqrtf(s2 * (1.f / 64.f) - mu * mu + EPSV);
                float partial = 0.f;
                #pragma unroll
                for (int j = 0; j < 4; j++) {
                    float v = fmaxf((acc2[i][j] - mu) * inv * LG2s[kq * 4 + j] + LB2s[kq * 4 + j], 0.f);
                    partial += v * HWos[kq * 4 + j];
                }
                #pragma unroll
                for (int o = 8; o > 0; o >>= 1)
                    partial += __shfl_xor_sync(0xffffffffu, partial, o);
                if (kq == 0) {
                    int s = sg2 * 2 + i;
                    if (s < scnt) preds[g_idx[s0s + s]] = partial + hbo;
                }
            }
        }
        __syncthreads();   // h1/ft safe to overwrite next subtile
    }
}

// ----------------------- launch -----------------------
extern "C" void kernel_launch(void* const* d_in, const int* in_sizes, int n_in,
                              void* d_out, int out_size) {
    const float* x      = (const float*)d_in[0];
    const int*   labels = (const int*)  d_in[1];
    const float *W0 = (const float*)d_in[2],  *b0 = (const float*)d_in[3],
                *gg0 = (const float*)d_in[4], *be0 = (const float*)d_in[5],
                *m0 = (const float*)d_in[6],  *v0 = (const float*)d_in[7];
    const float *W1 = (const float*)d_in[8],  *b1 = (const float*)d_in[9],
                *gg1 = (const float*)d_in[10], *be1 = (const float*)d_in[11],
                *m1 = (const float*)d_in[12], *v1 = (const float*)d_in[13];
    const float *W2 = (const float*)d_in[14], *b2 = (const float*)d_in[15],
                *gg2 = (const float*)d_in[16], *be2 = (const float*)d_in[17],
                *m2 = (const float*)d_in[18], *v2 = (const float*)d_in[19];
    const float *HW1 = (const float*)d_in[20], *Hb1 = (const float*)d_in[21],
                *LG1 = (const float*)d_in[22], *LB1 = (const float*)d_in[23],
                *HW2 = (const float*)d_in[24], *Hb2 = (const float*)d_in[25],
                *LG2 = (const float*)d_in[26], *LB2 = (const float*)d_in[27],
                *HWo = (const float*)d_in[28], *Hbo = (const float*)d_in[29];
    float* preds = (float*)d_out;

    static bool attr_done = false;
    if (!attr_done) {
        cudaFuncSetAttribute(k_head, cudaFuncAttributeMaxDynamicSharedMemorySize,
                             SMEM_HEAD_BYTES);
        cudaFuncSetAttribute(k_gemm0b, cudaFuncAttributeMaxDynamicSharedMemorySize,
                             G0_SMEM);
        attr_done = true;
    }

    float* w1p; cudaGetSymbolAddress((void**)&w1p, g_W1p);
    float* w2p; cudaGetSymbolAddress((void**)&w2p, g_W2p);
    float* a1;  cudaGetSymbolAddress((void**)&a1,  g_alpha1);
    float* bt1; cudaGetSymbolAddress((void**)&bt1, g_beta1);
    float* a2;  cudaGetSymbolAddress((void**)&a2,  g_alpha2);
    float* bt2; cudaGetSymbolAddress((void**)&bt2, g_beta2);
    float* y1;  cudaGetSymbolAddress((void**)&y1,  g_Y1);
    float* y2;  cudaGetSymbolAddress((void**)&y2,  g_Y2);
    float* y3;  cudaGetSymbolAddress((void**)&y3,  g_Y3);

    // order chosen so GEMM0 is launch index 3 (the one ncu captures)
    k_prep<<<1024, 256>>>(W0, b0, gg0, be0, m0, v0,
                          W1, b1, gg1, be1, m1, v1,
                          W2, b2, gg2, be2, m2, v2);
    k_padx<<<BB, 256>>>(x);
    k_hist<<<256, 256>>>(labels);
    k_gemm0b<<<dim3(N0 / 128, BB / 128), 256, G0_SMEM>>>();
    k_gemm<<<dim3(N1 / 128, BB / 128), 256>>>(y1, w1p, a1, bt1, y2, N0, N1, 1);
    k_gemm<<<dim3(N2 / 128, BB / 128), 256>>>(y2, w2p, a2, bt2, y3, N1, N2, 0);
    k_scan32<<<1, 32>>>();
    k_scatter<<<256, 256>>>(labels);
    k_head<<<MAX_STILES, 256, SMEM_HEAD_BYTES>>>(HW1, Hb1, LG1, LB1,
                                                 HW2, Hb2, LG2, LB2,
                                                 HWo, Hbo, preds);
}